// round 1
// baseline (speedup 1.0000x reference)
#include <cuda_runtime.h>
#include <cstdint>

// Problem constants
#define NB 8
#define NN 2048
#define HH 512
#define MROWS (NB * NN)   // 16384

// ---------------------------------------------------------------------------
// Scratch (device globals — no allocation allowed)
// ---------------------------------------------------------------------------
__device__ float g_x[MROWS * HH];        // embedding output / residual
__device__ float g_h[MROWS * 1024];      // layer activations
__device__ float g_hw[MROWS * 1024];     // h @ W per layer
__device__ float g_esrc[MROWS];
__device__ float g_edst[MROWS];
__device__ float g_m[MROWS];
__device__ float g_rz[MROWS];
__device__ float g_Weff[6 * HH];
__device__ float g_beff[HH];

// ---------------------------------------------------------------------------
// Packed fp32x2 FMA (Blackwell; ptxas won't emit this from C++)
// ---------------------------------------------------------------------------
__device__ __forceinline__ void ffma2(float2& c, float2 a, float2 b) {
    asm("fma.rn.f32x2 %0, %1, %2, %0;"
        : "+l"(*reinterpret_cast<unsigned long long*>(&c))
        : "l"(*reinterpret_cast<unsigned long long*>(&a)),
          "l"(*reinterpret_cast<unsigned long long*>(&b)));
}

// ---------------------------------------------------------------------------
// Epilogues:
// 0: C = acc
// 1: C = relu(acc + bias)
// 2: C = acc + bias + X
// 3: C = X + relu(acc + bias)
// 4: C = (X + relu(acc + bias)) * act[row]
// ---------------------------------------------------------------------------
template <int EPI>
__device__ __forceinline__ void epilogue(
    float2 acc[8][4], float* __restrict__ C, int Nc, int m0, int n0,
    int ty, int tx,
    const float* __restrict__ bias, const float* __restrict__ X,
    const float* __restrict__ act)
{
    const int gc = n0 + tx * 8;
    float bv[8];
    if (EPI != 0) {
#pragma unroll
        for (int j = 0; j < 8; j++) bv[j] = bias[gc + j];
    }
#pragma unroll
    for (int i = 0; i < 8; i++) {
        const int gm = m0 + ty * 8 + i;
        float o[8];
#pragma unroll
        for (int j = 0; j < 4; j++) { o[2 * j] = acc[i][j].x; o[2 * j + 1] = acc[i][j].y; }
        if (EPI == 1) {
#pragma unroll
            for (int j = 0; j < 8; j++) o[j] = fmaxf(o[j] + bv[j], 0.f);
        } else if (EPI == 2) {
            const float* xr = X + (size_t)gm * Nc + gc;
#pragma unroll
            for (int j = 0; j < 8; j++) o[j] = o[j] + bv[j] + xr[j];
        } else if (EPI == 3) {
            const float* xr = X + (size_t)gm * Nc + gc;
#pragma unroll
            for (int j = 0; j < 8; j++) o[j] = xr[j] + fmaxf(o[j] + bv[j], 0.f);
        } else if (EPI == 4) {
            const float a = act[gm];
            const float* xr = X + (size_t)gm * Nc + gc;
#pragma unroll
            for (int j = 0; j < 8; j++) o[j] = (xr[j] + fmaxf(o[j] + bv[j], 0.f)) * a;
        }
        float4* cp = reinterpret_cast<float4*>(C + (size_t)gm * Nc + gc);
        cp[0] = make_float4(o[0], o[1], o[2], o[3]);
        cp[1] = make_float4(o[4], o[5], o[6], o[7]);
    }
}

// ---------------------------------------------------------------------------
// Generic 128x128x16 SGEMM (A row-major [M,K], B row-major [K,Nc]).
// All dims are exact tile multiples — no guards.
// ---------------------------------------------------------------------------
template <int EPI>
__global__ __launch_bounds__(256, 2) void gemm_w_kernel(
    const float* __restrict__ A, const float* __restrict__ Bm,
    float* __restrict__ C, int K, int Nc,
    const float* __restrict__ bias, const float* __restrict__ X,
    const float* __restrict__ act)
{
    __shared__ __align__(16) float As[16][128];
    __shared__ __align__(16) float Bs[16][128];
    const int tid = threadIdx.x;
    const int tx = tid & 15, ty = tid >> 4;
    const int m0 = blockIdx.y * 128;
    const int n0 = blockIdx.x * 128;

    float2 acc[8][4];
#pragma unroll
    for (int i = 0; i < 8; i++)
#pragma unroll
        for (int j = 0; j < 4; j++) acc[i][j] = make_float2(0.f, 0.f);

    for (int k0 = 0; k0 < K; k0 += 16) {
#pragma unroll
        for (int p = 0; p < 2; p++) {
            int lin = tid + p * 256;
            int row = lin >> 2;
            int kq = (lin & 3) << 2;
            float4 v = *reinterpret_cast<const float4*>(A + (size_t)(m0 + row) * K + k0 + kq);
            As[kq + 0][row] = v.x; As[kq + 1][row] = v.y;
            As[kq + 2][row] = v.z; As[kq + 3][row] = v.w;
        }
#pragma unroll
        for (int p = 0; p < 2; p++) {
            int lin = tid + p * 256;
            int kr = lin >> 5;
            int cq = (lin & 31) << 2;
            *reinterpret_cast<float4*>(&Bs[kr][cq]) =
                *reinterpret_cast<const float4*>(Bm + (size_t)(k0 + kr) * Nc + n0 + cq);
        }
        __syncthreads();
#pragma unroll
        for (int k = 0; k < 16; k++) {
            float4 a0 = *reinterpret_cast<const float4*>(&As[k][ty * 8]);
            float4 a1 = *reinterpret_cast<const float4*>(&As[k][ty * 8 + 4]);
            float4 b0 = *reinterpret_cast<const float4*>(&Bs[k][tx * 8]);
            float4 b1 = *reinterpret_cast<const float4*>(&Bs[k][tx * 8 + 4]);
            float av[8] = {a0.x, a0.y, a0.z, a0.w, a1.x, a1.y, a1.z, a1.w};
            float2 bv[4] = {make_float2(b0.x, b0.y), make_float2(b0.z, b0.w),
                            make_float2(b1.x, b1.y), make_float2(b1.z, b1.w)};
#pragma unroll
            for (int i = 0; i < 8; i++) {
                float2 aa = make_float2(av[i], av[i]);
#pragma unroll
                for (int j = 0; j < 4; j++) ffma2(acc[i][j], aa, bv[j]);
            }
        }
        __syncthreads();
    }
    epilogue<EPI>(acc, C, Nc, m0, n0, ty, tx, bias, X, act);
}

// ---------------------------------------------------------------------------
// Attention aggregation GEMM: C[t,f] = sum_s P[t,s] * hw[s,f] per batch.
// P generated on-the-fly from adjacency + rank-1 logits + softmax stats.
// ---------------------------------------------------------------------------
__device__ __forceinline__ float pcalc(int a, int s, int t, float esv,
                                       float ed, float mr, float rzv)
{
    float l = ed + esv;
    l = l > 0.f ? l : 0.2f * l;           // LeakyReLU(0.2)
    float p = __expf(l - mr) * rzv;
    return (a != 0 || s == t) ? p : 0.f;  // mask (adj transposed) | self-loop
}

template <int EPI>
__global__ __launch_bounds__(256, 2) void gemm_att_kernel(
    const int* __restrict__ adj, const float* __restrict__ hw,
    const float* __restrict__ bias, const float* __restrict__ X,
    float* __restrict__ C, int Fo)
{
    __shared__ __align__(16) float As[16][128];
    __shared__ __align__(16) float Bs[16][128];
    __shared__ float sEd[128], sM[128], sRz[128];
    const int tid = threadIdx.x;
    const int tx = tid & 15, ty = tid >> 4;
    const int bn = blockIdx.z;
    const int t0 = blockIdx.y * 128;
    const int n0 = blockIdx.x * 128;
    const int rowbase = bn * NN;

    if (tid < 128) {
        sEd[tid] = g_edst[rowbase + t0 + tid];
        sM[tid]  = g_m[rowbase + t0 + tid];
        sRz[tid] = g_rz[rowbase + t0 + tid];
    }
    const int* adj_b = adj + (size_t)bn * NN * NN;
    const float* es_b = g_esrc + rowbase;
    __syncthreads();

    float2 acc[8][4];
#pragma unroll
    for (int i = 0; i < 8; i++)
#pragma unroll
        for (int j = 0; j < 4; j++) acc[i][j] = make_float2(0.f, 0.f);

    for (int k0 = 0; k0 < NN; k0 += 16) {
#pragma unroll
        for (int p = 0; p < 2; p++) {
            int lin = tid + p * 256;
            int kr = lin >> 5;
            int cq = (lin & 31) << 2;
            int s = k0 + kr;
            int4 av = *reinterpret_cast<const int4*>(adj_b + (size_t)s * NN + t0 + cq);
            float esv = es_b[s];
            As[kr][cq + 0] = pcalc(av.x, s, t0 + cq + 0, esv, sEd[cq + 0], sM[cq + 0], sRz[cq + 0]);
            As[kr][cq + 1] = pcalc(av.y, s, t0 + cq + 1, esv, sEd[cq + 1], sM[cq + 1], sRz[cq + 1]);
            As[kr][cq + 2] = pcalc(av.z, s, t0 + cq + 2, esv, sEd[cq + 2], sM[cq + 2], sRz[cq + 2]);
            As[kr][cq + 3] = pcalc(av.w, s, t0 + cq + 3, esv, sEd[cq + 3], sM[cq + 3], sRz[cq + 3]);
            *reinterpret_cast<float4*>(&Bs[kr][cq]) =
                *reinterpret_cast<const float4*>(hw + (size_t)(rowbase + s) * Fo + n0 + cq);
        }
        __syncthreads();
#pragma unroll
        for (int k = 0; k < 16; k++) {
            float4 a0 = *reinterpret_cast<const float4*>(&As[k][ty * 8]);
            float4 a1 = *reinterpret_cast<const float4*>(&As[k][ty * 8 + 4]);
            float4 b0 = *reinterpret_cast<const float4*>(&Bs[k][tx * 8]);
            float4 b1 = *reinterpret_cast<const float4*>(&Bs[k][tx * 8 + 4]);
            float av2[8] = {a0.x, a0.y, a0.z, a0.w, a1.x, a1.y, a1.z, a1.w};
            float2 bv[4] = {make_float2(b0.x, b0.y), make_float2(b0.z, b0.w),
                            make_float2(b1.x, b1.y), make_float2(b1.z, b1.w)};
#pragma unroll
            for (int i = 0; i < 8; i++) {
                float2 aa = make_float2(av2[i], av2[i]);
#pragma unroll
                for (int j = 0; j < 4; j++) ffma2(acc[i][j], aa, bv[j]);
            }
        }
        __syncthreads();
    }
    epilogue<EPI>(acc, C, Fo, rowbase + t0, n0, ty, tx, bias, X, nullptr);
}

// ---------------------------------------------------------------------------
// Weff = emb_W1 @ emb_W2 ; beff = emb_b1 @ emb_W2 + emb_b2
// ---------------------------------------------------------------------------
__global__ void prep_weff_kernel(const float* __restrict__ W1, const float* __restrict__ b1,
                                 const float* __restrict__ W2, const float* __restrict__ b2)
{
    int j = blockIdx.x * 256 + threadIdx.x;
    if (j >= HH) return;
    float acc[6] = {0.f, 0.f, 0.f, 0.f, 0.f, 0.f};
    float bacc = b2[j];
    for (int k = 0; k < HH; k++) {
        float w2 = W2[k * HH + j];
        bacc += b1[k] * w2;
#pragma unroll
        for (int i = 0; i < 6; i++) acc[i] += W1[i * HH + k] * w2;
    }
#pragma unroll
    for (int i = 0; i < 6; i++) g_Weff[i * HH + j] = acc[i];
    g_beff[j] = bacc;
}

// ---------------------------------------------------------------------------
// Feature construction + fused 6->512 embedding
// ---------------------------------------------------------------------------
__global__ void embed_kernel(const float* __restrict__ arr, const float* __restrict__ dep,
                             const float* __restrict__ hard,
                             const float* __restrict__ ts, const float* __restrict__ tt)
{
    int idx = blockIdx.x * 256 + threadIdx.x;   // < MROWS*HH
    int j = idx & (HH - 1);
    int row = idx >> 9;
    int b = row >> 11;
    float t = ts[b], T = tt[b];
    float ar = arr[row], de = dep[row];
    float f[6];
    f[0] = (t - ar) / (de - ar);
    f[1] = t / T;
    f[2] = fmodf(f[1], 2.f);
    f[3] = fmodf(f[1], 4.f);
    f[4] = fmodf(f[1], 7.f);
    f[5] = hard[row];
    float acc = g_beff[j];
#pragma unroll
    for (int i = 0; i < 6; i++) acc += f[i] * g_Weff[i * HH + j];
    g_x[idx] = acc;
}

// ---------------------------------------------------------------------------
// e_src / e_dst: per-row dot of hw with attention vectors
// ---------------------------------------------------------------------------
__global__ void e_kernel(const float* __restrict__ asrc, const float* __restrict__ adst, int Fo)
{
    int row = blockIdx.x;
    const float* h = g_hw + (size_t)row * Fo;
    float ps = 0.f, pd = 0.f;
    for (int f = threadIdx.x; f < Fo; f += 128) {
        float v = h[f];
        ps += v * asrc[f];
        pd += v * adst[f];
    }
#pragma unroll
    for (int off = 16; off; off >>= 1) {
        ps += __shfl_xor_sync(0xFFFFFFFFu, ps, off);
        pd += __shfl_xor_sync(0xFFFFFFFFu, pd, off);
    }
    __shared__ float sp[4], sd[4];
    int w = threadIdx.x >> 5, l = threadIdx.x & 31;
    if (l == 0) { sp[w] = ps; sd[w] = pd; }
    __syncthreads();
    if (threadIdx.x == 0) {
        g_esrc[row] = sp[0] + sp[1] + sp[2] + sp[3];
        g_edst[row] = sd[0] + sd[1] + sd[2] + sd[3];
    }
}

// ---------------------------------------------------------------------------
// Online masked-softmax stats: per (b,t) row max and 1/Z over valid sources.
// Block = 32 warps, each warp owns one t; adjacency tiles transposed in smem
// so the gmem reads stay coalesced despite the [s,t] -> [t,s] transpose.
// ---------------------------------------------------------------------------
__global__ __launch_bounds__(1024) void stats_kernel(const int* __restrict__ adj)
{
    int b = blockIdx.y;
    int t0 = blockIdx.x * 32;
    const int* adj_b = adj + (size_t)b * NN * NN;
    __shared__ int sa[32][33];
    int w = threadIdx.x >> 5;
    int l = threadIdx.x & 31;
    int t = t0 + w;
    float ed = g_edst[b * NN + t];
    float m = -1e30f, z = 0.f;
    for (int s0 = 0; s0 < NN; s0 += 32) {
        __syncthreads();
        sa[w][l] = adj_b[(size_t)(s0 + w) * NN + t0 + l];
        __syncthreads();
        int a = sa[l][w];
        int s = s0 + l;
        if (a != 0 || s == t) {
            float lg = ed + g_esrc[b * NN + s];
            lg = lg > 0.f ? lg : 0.2f * lg;
            float mn = fmaxf(m, lg);
            z = z * __expf(m - mn) + __expf(lg - mn);
            m = mn;
        }
    }
    float M = m;
#pragma unroll
    for (int off = 16; off; off >>= 1) M = fmaxf(M, __shfl_xor_sync(0xFFFFFFFFu, M, off));
    float zz = z * __expf(m - M);
#pragma unroll
    for (int off = 16; off; off >>= 1) zz += __shfl_xor_sync(0xFFFFFFFFu, zz, off);
    if (l == 0) {
        g_m[b * NN + t] = M;
        g_rz[b * NN + t] = 1.f / zz;
    }
}

// ---------------------------------------------------------------------------
// Host launcher
// ---------------------------------------------------------------------------
extern "C" void kernel_launch(void* const* d_in, const int* in_sizes, int n_in,
                              void* d_out, int out_size)
{
    const int*   adj      = (const int*)d_in[0];
    const float* arrivals = (const float*)d_in[1];
    const float* depart   = (const float*)d_in[2];
    const float* hard     = (const float*)d_in[3];
    const float* active   = (const float*)d_in[4];
    const float* timestep = (const float*)d_in[5];
    const float* totalts  = (const float*)d_in[6];
    const float* embW1 = (const float*)d_in[7];
    const float* embb1 = (const float*)d_in[8];
    const float* embW2 = (const float*)d_in[9];
    const float* embb2 = (const float*)d_in[10];
    const float* gatW[3]    = {(const float*)d_in[11], (const float*)d_in[15], (const float*)d_in[19]};
    const float* gatAsrc[3] = {(const float*)d_in[12], (const float*)d_in[16], (const float*)d_in[20]};
    const float* gatAdst[3] = {(const float*)d_in[13], (const float*)d_in[17], (const float*)d_in[21]};
    const float* gatB[3]    = {(const float*)d_in[14], (const float*)d_in[18], (const float*)d_in[22]};
    const float* ffW1 = (const float*)d_in[23];
    const float* ffb1 = (const float*)d_in[24];
    const float* ffW2 = (const float*)d_in[25];
    const float* ffb2 = (const float*)d_in[26];

    float *x, *h, *hw;
    cudaGetSymbolAddress((void**)&x,  g_x);
    cudaGetSymbolAddress((void**)&h,  g_h);
    cudaGetSymbolAddress((void**)&hw, g_hw);

    // Embedding
    prep_weff_kernel<<<2, 256>>>(embW1, embb1, embW2, embb2);
    embed_kernel<<<(MROWS * HH) / 256, 256>>>(arrivals, depart, hard, timestep, totalts);

    const int Kin[3] = {HH, 1024, 1024};
    const int Fo[3]  = {1024, 1024, HH};

    for (int l = 0; l < 3; l++) {
        const float* hin = (l == 0) ? x : h;
        // hw = h @ W
        gemm_w_kernel<0><<<dim3(Fo[l] / 128, MROWS / 128), 256>>>(
            hin, gatW[l], hw, Kin[l], Fo[l], nullptr, nullptr, nullptr);
        // e_src / e_dst
        e_kernel<<<MROWS, 128>>>(gatAsrc[l], gatAdst[l], Fo[l]);
        // softmax stats
        stats_kernel<<<dim3(NN / 32, NB), 1024>>>(adj);
        // aggregation (+bias, +relu for layers 0/1; +bias +x residual for layer 2)
        if (l < 2) {
            gemm_att_kernel<1><<<dim3(Fo[l] / 128, NN / 128, NB), 256>>>(
                adj, hw, gatB[l], nullptr, h, Fo[l]);
        } else {
            gemm_att_kernel<2><<<dim3(Fo[l] / 128, NN / 128, NB), 256>>>(
                adj, hw, gatB[l], x, h, Fo[l]);
        }
    }

    // ff1: x2 = x1 + relu(x1 @ W + b)   (x1 lives in g_h, width 512)
    gemm_w_kernel<3><<<dim3(HH / 128, MROWS / 128), 256>>>(
        h, ffW1, x, HH, HH, ffb1, h, nullptr);
    // ff2: out = (x2 + relu(x2 @ W + b)) * active
    gemm_w_kernel<4><<<dim3(HH / 128, MROWS / 128), 256>>>(
        x, ffW2, (float*)d_out, HH, HH, ffb2, x, active);
}

// round 3
// speedup vs baseline: 2.0139x; 2.0139x over previous
#include <cuda_runtime.h>
#include <cstdint>

#define NB 8
#define NN 2048
#define HH 512
#define MROWS (NB * NN)   // 16384

// ---------------------------------------------------------------------------
// Scratch (device globals — no allocation allowed)
// ---------------------------------------------------------------------------
__device__ float g_x[MROWS * HH];                 // embedding output / residual
__device__ float g_h[MROWS * 1024];               // layer activations
__device__ float g_hw[MROWS * 1024];              // h @ W (tf32-rounded)
__device__ float g_P[(size_t)MROWS * NN];         // unnormalized attention (tf32-rounded)
__device__ uint32_t g_adjT[MROWS * (NN / 32)];    // bit: valid(t, s), self-loop folded
__device__ float g_esrc[MROWS], g_edst[MROWS];
__device__ float g_f1[MROWS], g_f2[MROWS];        // per-source exp factors
__device__ float g_qa[MROWS], g_qb[MROWS];        // per-target exp factors
__device__ float g_rz[MROWS];                     // 1 / row-sum of P'
__device__ unsigned int g_smax_bits[NB];          // orderable-int max of esrc per batch
__device__ float g_Weff[6 * HH];
__device__ float g_beff[HH];

// ---------------------------------------------------------------------------
// Helpers
// ---------------------------------------------------------------------------
__device__ __forceinline__ float cvt_tf32f(float x) {
    uint32_t r;
    asm("cvt.rna.tf32.f32 %0, %1;" : "=r"(r) : "f"(x));
    return __uint_as_float(r);
}
__device__ __forceinline__ unsigned enc_ord(float f) {
    unsigned i = __float_as_uint(f);
    return (i & 0x80000000u) ? ~i : (i | 0x80000000u);
}
__device__ __forceinline__ float dec_ord(unsigned k) {
    unsigned i = (k & 0x80000000u) ? (k & 0x7FFFFFFFu) : ~k;
    return __uint_as_float(i);
}
__device__ __forceinline__ void mma8(float* c, const float* a, const float* b) {
    asm volatile(
        "mma.sync.aligned.m16n8k8.row.col.f32.tf32.tf32.f32 "
        "{%0,%1,%2,%3}, {%4,%5,%6,%7}, {%8,%9}, {%0,%1,%2,%3};"
        : "+f"(c[0]), "+f"(c[1]), "+f"(c[2]), "+f"(c[3])
        : "r"(__float_as_uint(a[0])), "r"(__float_as_uint(a[1])),
          "r"(__float_as_uint(a[2])), "r"(__float_as_uint(a[3])),
          "r"(__float_as_uint(b[0])), "r"(__float_as_uint(b[1])));
}

// smem tile geometry: pitch 136 floats -> conflict-free fragment loads
#define PITCH 136
#define TILEF (32 * PITCH)            // floats per operand tile
#define STAGEF (2 * TILEF)            // A + B
#define SMEM_BYTES (2 * STAGEF * 4)   // 2 stages = 69632 B

// ---------------------------------------------------------------------------
// Unified tf32 tensor-core GEMM. C[M,N] = A[M,K] @ B[K,N] (both row-major).
// EPI 0: C = cvt_tf32(acc)                       (hw pass; inputs cvt'd here)
// EPI 1: C = relu(acc*rz + bias)                 (attention, batched; A,B pre-tf32)
// EPI 2: C = acc*rz + bias + X                   (attention last, batched)
// EPI 3: C = X + relu(acc + bias)                (ff1)
// EPI 4: C = (X + relu(acc + bias)) * act[row]   (ff2)
// ---------------------------------------------------------------------------
template <int EPI>
__global__ __launch_bounds__(256, 2) void gemm_tc(
    const float* __restrict__ A, const float* __restrict__ B, float* __restrict__ C,
    int K, int N, const float* __restrict__ bias, const float* __restrict__ X,
    const float* __restrict__ act, const float* __restrict__ rz)
{
    constexpr bool BATCHED = (EPI == 1 || EPI == 2);
    constexpr bool CVT = !BATCHED;   // attention operands are already tf32-rounded
    extern __shared__ float smf[];
    const int tid = threadIdx.x;
    const int lane = tid & 31, wid = tid >> 5;
    const int m0 = blockIdx.y * 128, n0 = blockIdx.x * 128;
    const int wm = (wid >> 2) * 64, wn = (wid & 3) * 32;

    size_t zoff = 0;
    if (BATCHED) zoff = (size_t)blockIdx.z * NN;
    const float* Ab = A + zoff * K;
    const float* Bb = B + zoff * N;
    float* Cb = C + zoff * N;
    const float* Xb = (EPI == 2 || EPI == 3 || EPI == 4) ? X + zoff * N : nullptr;
    const float* rzb = BATCHED ? rz + zoff : nullptr;

    float acc[4][4][4];
#pragma unroll
    for (int i = 0; i < 4; i++)
#pragma unroll
        for (int j = 0; j < 4; j++)
#pragma unroll
            for (int q = 0; q < 4; q++) acc[i][j][q] = 0.f;

    auto load_tile = [&](int k0, int stg) {
        float* sA = smf + stg * STAGEF;
        float* sB = sA + TILEF;
#pragma unroll
        for (int p = 0; p < 4; p++) {
            int lin = tid + p * 256;
            int row = lin >> 3, kq = (lin & 7) << 2;
            float4 v = *reinterpret_cast<const float4*>(Ab + (size_t)(m0 + row) * K + k0 + kq);
            if (CVT) { v.x = cvt_tf32f(v.x); v.y = cvt_tf32f(v.y); v.z = cvt_tf32f(v.z); v.w = cvt_tf32f(v.w); }
            sA[(kq + 0) * PITCH + row] = v.x;
            sA[(kq + 1) * PITCH + row] = v.y;
            sA[(kq + 2) * PITCH + row] = v.z;
            sA[(kq + 3) * PITCH + row] = v.w;
        }
#pragma unroll
        for (int p = 0; p < 4; p++) {
            int lin = tid + p * 256;
            int row = lin >> 5, nq = (lin & 31) << 2;
            float4 v = *reinterpret_cast<const float4*>(Bb + (size_t)(k0 + row) * N + n0 + nq);
            if (CVT) { v.x = cvt_tf32f(v.x); v.y = cvt_tf32f(v.y); v.z = cvt_tf32f(v.z); v.w = cvt_tf32f(v.w); }
            *reinterpret_cast<float4*>(&sB[row * PITCH + nq]) = v;
        }
    };

    load_tile(0, 0);
    __syncthreads();
    const int nkt = K >> 5;
    for (int kt = 0; kt < nkt; kt++) {
        const float* sA = smf + (kt & 1) * STAGEF;
        const float* sB = sA + TILEF;
#pragma unroll
        for (int kk = 0; kk < 32; kk += 8) {
            float a[4][4], b[4][2];
            const int ak = kk + (lane & 3);
            const int am = lane >> 2;
#pragma unroll
            for (int mf = 0; mf < 4; mf++) {
                int r = wm + mf * 16 + am;
                a[mf][0] = sA[ak * PITCH + r];
                a[mf][1] = sA[ak * PITCH + r + 8];
                a[mf][2] = sA[(ak + 4) * PITCH + r];
                a[mf][3] = sA[(ak + 4) * PITCH + r + 8];
            }
#pragma unroll
            for (int nf = 0; nf < 4; nf++) {
                int c = wn + nf * 8 + am;
                b[nf][0] = sB[ak * PITCH + c];
                b[nf][1] = sB[(ak + 4) * PITCH + c];
            }
#pragma unroll
            for (int mf = 0; mf < 4; mf++)
#pragma unroll
                for (int nf = 0; nf < 4; nf++) mma8(acc[mf][nf], a[mf], b[nf]);
        }
        if (kt + 1 < nkt) load_tile((kt + 1) << 5, (kt + 1) & 1);
        __syncthreads();
    }

    // Epilogue
#pragma unroll
    for (int mf = 0; mf < 4; mf++) {
#pragma unroll
        for (int rr = 0; rr < 2; rr++) {
            const int r = m0 + wm + mf * 16 + (lane >> 2) + rr * 8;
            float rzv = 1.f, actv = 1.f;
            if (BATCHED) rzv = rzb[r];
            if (EPI == 4) actv = act[r];
#pragma unroll
            for (int nf = 0; nf < 4; nf++) {
                const int cc = n0 + wn + nf * 8 + (lane & 3) * 2;
                float v0 = acc[mf][nf][rr * 2 + 0];
                float v1 = acc[mf][nf][rr * 2 + 1];
                if (BATCHED) { v0 *= rzv; v1 *= rzv; }
                if (EPI >= 1) { v0 += bias[cc]; v1 += bias[cc + 1]; }
                if (EPI == 1) { v0 = fmaxf(v0, 0.f); v1 = fmaxf(v1, 0.f); }
                else if (EPI == 2) {
                    const float* xr = Xb + (size_t)r * N + cc;
                    v0 += xr[0]; v1 += xr[1];
                } else if (EPI == 3) {
                    const float* xr = Xb + (size_t)r * N + cc;
                    v0 = xr[0] + fmaxf(v0, 0.f); v1 = xr[1] + fmaxf(v1, 0.f);
                } else if (EPI == 4) {
                    const float* xr = Xb + (size_t)r * N + cc;
                    v0 = (xr[0] + fmaxf(v0, 0.f)) * actv;
                    v1 = (xr[1] + fmaxf(v1, 0.f)) * actv;
                } else if (EPI == 0) {
                    v0 = cvt_tf32f(v0); v1 = cvt_tf32f(v1);
                }
                *reinterpret_cast<float2*>(Cb + (size_t)r * N + cc) = make_float2(v0, v1);
            }
        }
    }
}

// ---------------------------------------------------------------------------
// adjT: bit s of word (b,t,s/32) = (adj[b][s][t]!=0) | (s==t)
// 32x32 int tile -> ballot transpose
// ---------------------------------------------------------------------------
__global__ __launch_bounds__(1024) void adjT_kernel(const int* __restrict__ adj)
{
    __shared__ int sa[32][33];
    const int b = blockIdx.z, t0 = blockIdx.y * 32, s0 = blockIdx.x * 32;
    const int w = threadIdx.x >> 5, lane = threadIdx.x & 31;
    sa[w][lane] = adj[((size_t)b * NN + s0 + w) * NN + t0 + lane];
    __syncthreads();
    const int t = t0 + w;
    uint32_t word = __ballot_sync(0xFFFFFFFFu, sa[lane][w] != 0);
    if (lane == 0) {
        if ((t >> 5) == (s0 >> 5)) word |= 1u << (t & 31);
        g_adjT[((size_t)b * NN + t) * (NN / 32) + (s0 >> 5)] = word;
    }
}

// ---------------------------------------------------------------------------
// Weff = emb_W1 @ emb_W2 ; beff = emb_b1 @ emb_W2 + emb_b2
// ---------------------------------------------------------------------------
__global__ void prep_weff_kernel(const float* __restrict__ W1, const float* __restrict__ b1,
                                 const float* __restrict__ W2, const float* __restrict__ b2)
{
    int j = blockIdx.x * 256 + threadIdx.x;
    if (j >= HH) return;
    float acc[6] = {0.f, 0.f, 0.f, 0.f, 0.f, 0.f};
    float bacc = b2[j];
    for (int k = 0; k < HH; k++) {
        float w2 = W2[k * HH + j];
        bacc += b1[k] * w2;
#pragma unroll
        for (int i = 0; i < 6; i++) acc[i] += W1[i * HH + k] * w2;
    }
#pragma unroll
    for (int i = 0; i < 6; i++) g_Weff[i * HH + j] = acc[i];
    g_beff[j] = bacc;
}

// ---------------------------------------------------------------------------
// Feature construction + fused 6->512 embedding
// ---------------------------------------------------------------------------
__global__ void embed_kernel(const float* __restrict__ arr, const float* __restrict__ dep,
                             const float* __restrict__ hard,
                             const float* __restrict__ ts, const float* __restrict__ tt)
{
    int idx = blockIdx.x * 256 + threadIdx.x;
    int j = idx & (HH - 1);
    int row = idx >> 9;
    int b = row >> 11;
    float t = ts[b], T = tt[b];
    float ar = arr[row], de = dep[row];
    float f[6];
    f[0] = (t - ar) / (de - ar);
    f[1] = t / T;
    f[2] = fmodf(f[1], 2.f);
    f[3] = fmodf(f[1], 4.f);
    f[4] = fmodf(f[1], 7.f);
    f[5] = hard[row];
    float acc = g_beff[j];
#pragma unroll
    for (int i = 0; i < 6; i++) acc += f[i] * g_Weff[i * HH + j];
    g_x[idx] = acc;
}

// ---------------------------------------------------------------------------
// e_src / e_dst per row + per-batch max(e_src) via orderable-int atomicMax
// ---------------------------------------------------------------------------
__global__ void reset_smax_kernel()
{
    if (threadIdx.x < NB) g_smax_bits[threadIdx.x] = 0x007FFFFFu;  // enc(-inf)
}

__global__ void e_kernel(const float* __restrict__ asrc, const float* __restrict__ adst, int Fo)
{
    int row = blockIdx.x;
    const float* h = g_hw + (size_t)row * Fo;
    float ps = 0.f, pd = 0.f;
    for (int f = threadIdx.x; f < Fo; f += 128) {
        float v = h[f];
        ps += v * asrc[f];
        pd += v * adst[f];
    }
#pragma unroll
    for (int off = 16; off; off >>= 1) {
        ps += __shfl_xor_sync(0xFFFFFFFFu, ps, off);
        pd += __shfl_xor_sync(0xFFFFFFFFu, pd, off);
    }
    __shared__ float sp[4], sd[4];
    int w = threadIdx.x >> 5, l = threadIdx.x & 31;
    if (l == 0) { sp[w] = ps; sd[w] = pd; }
    __syncthreads();
    if (threadIdx.x == 0) {
        float es = sp[0] + sp[1] + sp[2] + sp[3];
        g_esrc[row] = es;
        g_edst[row] = sd[0] + sd[1] + sd[2] + sd[3];
        atomicMax(&g_smax_bits[row >> 11], enc_ord(es));
    }
}

// ---------------------------------------------------------------------------
// Per-node exp factors. All exponents <= 0 by construction (no overflow).
// P'(t,s) = valid * max(qa_t*f1_s, qb_t*f2_s) = valid * exp(leaky(ed+es) - mhat_t)
// ---------------------------------------------------------------------------
__global__ void nodeprep_kernel()
{
    int t = blockIdx.x * 256 + threadIdx.x;
    int b = t >> 11;
    float sm = dec_ord(g_smax_bits[b]);
    float es = g_esrc[t], ed = g_edst[t];
    g_f1[t] = __expf(es - sm);
    g_f2[t] = __expf(0.2f * (es - sm));
    float u = ed + sm;
    float mh = fmaxf(u, 0.2f * u);
    g_qa[t] = __expf(u - mh);
    g_qb[t] = __expf(0.2f * u - mh);
}

// ---------------------------------------------------------------------------
// Materialize P' (tf32-rounded, so row sums match exactly what the MMA sees)
// + fused row-sum -> g_rz. One warp per target row.
// ---------------------------------------------------------------------------
__global__ __launch_bounds__(256) void pgen_kernel()
{
    const int wid = threadIdx.x >> 5, lane = threadIdx.x & 31;
    const int t = blockIdx.x * 8 + wid;
    const int b = t >> 11;
    const float qa = g_qa[t], qb = g_qb[t];
    const uint32_t* wrow = g_adjT + (size_t)t * (NN / 32);
    const float* f1 = g_f1 + b * NN;
    const float* f2 = g_f2 + b * NN;
    float* Prow = g_P + (size_t)t * NN;
    float sum = 0.f;
#pragma unroll 4
    for (int i = 0; i < 16; i++) {
        const int s = i * 128 + lane * 4;
        const uint32_t w = wrow[s >> 5];
        const uint32_t sh = s & 31;
        float4 x1 = *reinterpret_cast<const float4*>(f1 + s);
        float4 x2 = *reinterpret_cast<const float4*>(f2 + s);
        float4 o;
        o.x = ((w >> (sh + 0)) & 1u) ? cvt_tf32f(fmaxf(qa * x1.x, qb * x2.x)) : 0.f;
        o.y = ((w >> (sh + 1)) & 1u) ? cvt_tf32f(fmaxf(qa * x1.y, qb * x2.y)) : 0.f;
        o.z = ((w >> (sh + 2)) & 1u) ? cvt_tf32f(fmaxf(qa * x1.z, qb * x2.z)) : 0.f;
        o.w = ((w >> (sh + 3)) & 1u) ? cvt_tf32f(fmaxf(qa * x1.w, qb * x2.w)) : 0.f;
        sum += (o.x + o.y) + (o.z + o.w);
        *reinterpret_cast<float4*>(Prow + s) = o;
    }
#pragma unroll
    for (int off = 16; off; off >>= 1) sum += __shfl_xor_sync(0xFFFFFFFFu, sum, off);
    if (lane == 0) g_rz[t] = 1.f / fmaxf(sum, 1e-30f);
}

// ---------------------------------------------------------------------------
// Host launcher
// ---------------------------------------------------------------------------
extern "C" void kernel_launch(void* const* d_in, const int* in_sizes, int n_in,
                              void* d_out, int out_size)
{
    const int*   adj      = (const int*)d_in[0];
    const float* arrivals = (const float*)d_in[1];
    const float* depart   = (const float*)d_in[2];
    const float* hard     = (const float*)d_in[3];
    const float* active   = (const float*)d_in[4];
    const float* timestep = (const float*)d_in[5];
    const float* totalts  = (const float*)d_in[6];
    const float* embW1 = (const float*)d_in[7];
    const float* embb1 = (const float*)d_in[8];
    const float* embW2 = (const float*)d_in[9];
    const float* embb2 = (const float*)d_in[10];
    const float* gatW[3]    = {(const float*)d_in[11], (const float*)d_in[15], (const float*)d_in[19]};
    const float* gatAsrc[3] = {(const float*)d_in[12], (const float*)d_in[16], (const float*)d_in[20]};
    const float* gatAdst[3] = {(const float*)d_in[13], (const float*)d_in[17], (const float*)d_in[21]};
    const float* gatB[3]    = {(const float*)d_in[14], (const float*)d_in[18], (const float*)d_in[22]};
    const float* ffW1 = (const float*)d_in[23];
    const float* ffb1 = (const float*)d_in[24];
    const float* ffW2 = (const float*)d_in[25];
    const float* ffb2 = (const float*)d_in[26];

    float *x, *h, *hw, *P, *rz;
    cudaGetSymbolAddress((void**)&x,  g_x);
    cudaGetSymbolAddress((void**)&h,  g_h);
    cudaGetSymbolAddress((void**)&hw, g_hw);
    cudaGetSymbolAddress((void**)&P,  g_P);
    cudaGetSymbolAddress((void**)&rz, g_rz);

    static int smem_set = 0;
    if (!smem_set) {
        cudaFuncSetAttribute(gemm_tc<0>, cudaFuncAttributeMaxDynamicSharedMemorySize, SMEM_BYTES);
        cudaFuncSetAttribute(gemm_tc<1>, cudaFuncAttributeMaxDynamicSharedMemorySize, SMEM_BYTES);
        cudaFuncSetAttribute(gemm_tc<2>, cudaFuncAttributeMaxDynamicSharedMemorySize, SMEM_BYTES);
        cudaFuncSetAttribute(gemm_tc<3>, cudaFuncAttributeMaxDynamicSharedMemorySize, SMEM_BYTES);
        cudaFuncSetAttribute(gemm_tc<4>, cudaFuncAttributeMaxDynamicSharedMemorySize, SMEM_BYTES);
        smem_set = 1;
    }

    prep_weff_kernel<<<2, 256>>>(embW1, embb1, embW2, embb2);
    embed_kernel<<<(MROWS * HH) / 256, 256>>>(arrivals, depart, hard, timestep, totalts);
    adjT_kernel<<<dim3(NN / 32, NN / 32, NB), 1024>>>(adj);

    const int Kin[3] = {HH, 1024, 1024};
    const int Fo[3]  = {1024, 1024, HH};

    for (int l = 0; l < 3; l++) {
        const float* hin = (l == 0) ? x : h;
        // hw = hin @ W  (tf32-rounded store)
        gemm_tc<0><<<dim3(Fo[l] / 128, MROWS / 128), 256, SMEM_BYTES>>>(
            hin, gatW[l], hw, Kin[l], Fo[l], nullptr, nullptr, nullptr, nullptr);
        reset_smax_kernel<<<1, 32>>>();
        e_kernel<<<MROWS, 128>>>(gatAsrc[l], gatAdst[l], Fo[l]);
        nodeprep_kernel<<<MROWS / 256, 256>>>();
        pgen_kernel<<<MROWS / 8, 256>>>();
        if (l < 2) {
            gemm_tc<1><<<dim3(Fo[l] / 128, NN / 128, NB), 256, SMEM_BYTES>>>(
                P, hw, h, NN, Fo[l], gatB[l], nullptr, nullptr, rz);
        } else {
            gemm_tc<2><<<dim3(Fo[l] / 128, NN / 128, NB), 256, SMEM_BYTES>>>(
                P, hw, h, NN, Fo[l], gatB[l], x, nullptr, rz);
        }
    }

    // ff1: x2 = x1 + relu(x1 @ W1 + b1)
    gemm_tc<3><<<dim3(HH / 128, MROWS / 128), 256, SMEM_BYTES>>>(
        h, ffW1, x, HH, HH, ffb1, h, nullptr, nullptr);
    // ff2: out = (x2 + relu(x2 @ W2 + b2)) * active
    gemm_tc<4><<<dim3(HH / 128, MROWS / 128), 256, SMEM_BYTES>>>(
        x, ffW2, (float*)d_out, HH, HH, ffb2, x, active, nullptr);
}

// round 4
// speedup vs baseline: 2.5594x; 1.2709x over previous
#include <cuda_runtime.h>
#include <cstdint>

#define NB 8
#define NN 2048
#define HH 512
#define MROWS (NB * NN)   // 16384

// ---------------------------------------------------------------------------
// Scratch (device globals — no allocation allowed)
// ---------------------------------------------------------------------------
__device__ float g_x[MROWS * HH];                 // embedding output / residual
__device__ float g_h[MROWS * 1024];               // layer activations
__device__ float g_hw[MROWS * 1024];              // h @ W (tf32-rounded)
__device__ float g_P[(size_t)MROWS * NN];         // unnormalized attention (tf32-rounded)
__device__ uint32_t g_adjT[MROWS * (NN / 32)];    // bit: valid(t, s), self-loop folded
__device__ float g_esrc[MROWS], g_edst[MROWS];
__device__ float g_f1[MROWS], g_f2[MROWS];        // per-source exp factors
__device__ float g_qa[MROWS], g_qb[MROWS];        // per-target exp factors
__device__ float g_rz[MROWS];                     // 1 / row-sum of P'
__device__ unsigned int g_smax_bits[NB];          // orderable-int max of esrc per batch
__device__ float g_Weff[6 * HH];
__device__ float g_beff[HH];

// ---------------------------------------------------------------------------
// Helpers
// ---------------------------------------------------------------------------
__device__ __forceinline__ float cvt_tf32f(float x) {
    uint32_t r;
    asm("cvt.rna.tf32.f32 %0, %1;" : "=r"(r) : "f"(x));
    return __uint_as_float(r);
}
__device__ __forceinline__ unsigned enc_ord(float f) {
    unsigned i = __float_as_uint(f);
    return (i & 0x80000000u) ? ~i : (i | 0x80000000u);
}
__device__ __forceinline__ float dec_ord(unsigned k) {
    unsigned i = (k & 0x80000000u) ? (k & 0x7FFFFFFFu) : ~k;
    return __uint_as_float(i);
}
__device__ __forceinline__ void mma8(float* c, const float* a, const float* b) {
    asm volatile(
        "mma.sync.aligned.m16n8k8.row.col.f32.tf32.tf32.f32 "
        "{%0,%1,%2,%3}, {%4,%5,%6,%7}, {%8,%9}, {%0,%1,%2,%3};"
        : "+f"(c[0]), "+f"(c[1]), "+f"(c[2]), "+f"(c[3])
        : "r"(__float_as_uint(a[0])), "r"(__float_as_uint(a[1])),
          "r"(__float_as_uint(a[2])), "r"(__float_as_uint(a[3])),
          "r"(__float_as_uint(b[0])), "r"(__float_as_uint(b[1])));
}

// Fragment-major stage layout:
//  A region: 4096 floats. float4 slot index = (ws*16 + kk*4 + mf)*32 + lane'
//            lane' = ((m&7)<<2 | (k&3)) ^ kk ; reg = ((m>>3)&1) | (((k>>2)&1)<<1)
//  B region: 4096 floats. float2 slot index = (wcs*16 + kk*4 + nf)*32 + lane'
//            lane' = (((c&7)<<2) | (k&3)) ^ nf ^ (wcs<<2) ; reg = (k>>2)&1
#define STAGEF 8192                     // floats per stage (A 16KB + B 16KB)
#define SMEM_BYTES (2 * STAGEF * 4)     // 65536 B

// ---------------------------------------------------------------------------
// Unified tf32 tensor-core GEMM. C[M,N] = A[M,K] @ B[K,N] (both row-major).
// EPI 0: C = cvt_tf32(acc)                       (hw pass; inputs cvt'd here)
// EPI 1: C = relu(acc*rz + bias)                 (attention, batched; A,B pre-tf32)
// EPI 2: C = acc*rz + bias + X                   (attention last, batched)
// EPI 3: C = X + relu(acc + bias)                (ff1)
// EPI 4: C = (X + relu(acc + bias)) * act[row]   (ff2)
// ---------------------------------------------------------------------------
template <int EPI>
__global__ __launch_bounds__(256, 2) void gemm_tc(
    const float* __restrict__ A, const float* __restrict__ B, float* __restrict__ C,
    int K, int N, const float* __restrict__ bias, const float* __restrict__ X,
    const float* __restrict__ act, const float* __restrict__ rz)
{
    constexpr bool BATCHED = (EPI == 1 || EPI == 2);
    constexpr bool CVT = !BATCHED;   // attention operands are already tf32-rounded
    extern __shared__ float smf[];
    const int tid = threadIdx.x;
    const int lane = tid & 31, wid = tid >> 5;

    // CTA rasterization swizzle: 32-CTA groups = 4 m-rows x GX n-cols share L2
    int bx = blockIdx.x, by = blockIdx.y;
    {
        const int GX = gridDim.x;
        const int lin = by * GX + bx;
        const int grp = lin / (4 * GX);
        const int rem = lin - grp * 4 * GX;
        by = grp * 4 + (rem & 3);
        bx = rem >> 2;
    }
    const int m0 = by * 128, n0 = bx * 128;
    const int ws = wid >> 2, wcs = wid & 3;
    const int wm = ws * 64, wn = wcs * 32;

    size_t zoff = 0;
    if (BATCHED) zoff = (size_t)blockIdx.z * NN;
    const float* Ab = A + zoff * K;
    const float* Bb = B + zoff * N;
    float* Cb = C + zoff * N;
    const float* Xb = (EPI == 2 || EPI == 3 || EPI == 4) ? X + zoff * N : nullptr;
    const float* rzb = BATCHED ? rz + zoff : nullptr;

    float acc[4][4][4];
#pragma unroll
    for (int i = 0; i < 4; i++)
#pragma unroll
        for (int j = 0; j < 4; j++)
#pragma unroll
            for (int q = 0; q < 4; q++) acc[i][j][q] = 0.f;

    float4 va[4], vb[4];

    auto ldg = [&](int k0) {
#pragma unroll
        for (int p = 0; p < 4; p++) {
            const int lin = tid + p * 256;
            const int m = lin >> 3, kq = (lin & 7) << 2;
            va[p] = *reinterpret_cast<const float4*>(Ab + (size_t)(m0 + m) * K + k0 + kq);
            const int kr = lin >> 5, nq = (lin & 31) << 2;
            vb[p] = *reinterpret_cast<const float4*>(Bb + (size_t)(k0 + kr) * N + n0 + nq);
        }
        if (CVT) {
#pragma unroll
            for (int p = 0; p < 4; p++) {
                va[p].x = cvt_tf32f(va[p].x); va[p].y = cvt_tf32f(va[p].y);
                va[p].z = cvt_tf32f(va[p].z); va[p].w = cvt_tf32f(va[p].w);
                vb[p].x = cvt_tf32f(vb[p].x); vb[p].y = cvt_tf32f(vb[p].y);
                vb[p].z = cvt_tf32f(vb[p].z); vb[p].w = cvt_tf32f(vb[p].w);
            }
        }
    };

    auto sts = [&](int stg) {
        float* sA = smf + stg * STAGEF;
        float* sB = sA + 4096;
#pragma unroll
        for (int p = 0; p < 4; p++) {
            const int lin = tid + p * 256;
            {   // A element (m, kq+j)
                const int m = lin >> 3, kq = (lin & 7) << 2;
                const int kk = kq >> 3;
                const int slot = ((m >> 6) << 4) + (kk << 2) + ((m >> 4) & 3);
                const int reg = ((m >> 3) & 1) | (((kq >> 2) & 1) << 1);
                const int am4 = (m & 7) << 2;
                float* base = sA + slot * 128 + reg;
                base[(am4 | (0 ^ kk)) << 2] = va[p].x;
                base[(am4 | (1 ^ kk)) << 2] = va[p].y;
                base[(am4 | (2 ^ kk)) << 2] = va[p].z;
                base[(am4 | (3 ^ kk)) << 2] = va[p].w;
            }
            {   // B element (kr, nq+j)
                const int kr = lin >> 5, nq = (lin & 31) << 2;
                const int kk = kr >> 3, k3 = kr & 3, reg = (kr >> 2) & 1;
                const int nf = (nq >> 3) & 3, wc = nq >> 5, c4 = nq & 4;
                const int slot = (wc << 4) + (kk << 2) + nf;
                const int xr = nf ^ (wc << 2);
                float* base = sB + slot * 64 + reg;
                base[(((((c4 | 0) << 2) | k3) ^ xr)) << 1] = vb[p].x;
                base[(((((c4 | 1) << 2) | k3) ^ xr)) << 1] = vb[p].y;
                base[(((((c4 | 2) << 2) | k3) ^ xr)) << 1] = vb[p].z;
                base[(((((c4 | 3) << 2) | k3) ^ xr)) << 1] = vb[p].w;
            }
        }
    };

    auto compute = [&](int stg) {
        const float4* sA4 = reinterpret_cast<const float4*>(smf + stg * STAGEF);
        const float2* sB2 = reinterpret_cast<const float2*>(smf + stg * STAGEF + 4096);
#pragma unroll
        for (int kk = 0; kk < 4; kk++) {
            float4 fa[4]; float2 fb[4];
#pragma unroll
            for (int mf = 0; mf < 4; mf++)
                fa[mf] = sA4[((ws << 4) + (kk << 2) + mf) * 32 + (lane ^ kk)];
#pragma unroll
            for (int nf = 0; nf < 4; nf++)
                fb[nf] = sB2[((wcs << 4) + (kk << 2) + nf) * 32 + (lane ^ nf ^ (wcs << 2))];
#pragma unroll
            for (int mf = 0; mf < 4; mf++)
#pragma unroll
                for (int nf = 0; nf < 4; nf++)
                    mma8(acc[mf][nf], reinterpret_cast<const float*>(&fa[mf]),
                         reinterpret_cast<const float*>(&fb[nf]));
        }
    };

    ldg(0);
    sts(0);
    __syncthreads();
    const int nkt = K >> 5;
    for (int kt = 0; kt < nkt; kt++) {
        if (kt + 1 < nkt) ldg((kt + 1) << 5);
        compute(kt & 1);
        if (kt + 1 < nkt) {
            sts((kt + 1) & 1);
            __syncthreads();
        }
    }

    // Epilogue
#pragma unroll
    for (int mf = 0; mf < 4; mf++) {
#pragma unroll
        for (int rr = 0; rr < 2; rr++) {
            const int r = m0 + wm + mf * 16 + (lane >> 2) + rr * 8;
            float rzv = 1.f, actv = 1.f;
            if (BATCHED) rzv = rzb[r];
            if (EPI == 4) actv = act[r];
#pragma unroll
            for (int nf = 0; nf < 4; nf++) {
                const int cc = n0 + wn + nf * 8 + (lane & 3) * 2;
                float v0 = acc[mf][nf][rr * 2 + 0];
                float v1 = acc[mf][nf][rr * 2 + 1];
                if (BATCHED) { v0 *= rzv; v1 *= rzv; }
                if (EPI >= 1) { v0 += bias[cc]; v1 += bias[cc + 1]; }
                if (EPI == 1) { v0 = fmaxf(v0, 0.f); v1 = fmaxf(v1, 0.f); }
                else if (EPI == 2) {
                    const float* xr = Xb + (size_t)r * N + cc;
                    v0 += xr[0]; v1 += xr[1];
                } else if (EPI == 3) {
                    const float* xr = Xb + (size_t)r * N + cc;
                    v0 = xr[0] + fmaxf(v0, 0.f); v1 = xr[1] + fmaxf(v1, 0.f);
                } else if (EPI == 4) {
                    const float* xr = Xb + (size_t)r * N + cc;
                    v0 = (xr[0] + fmaxf(v0, 0.f)) * actv;
                    v1 = (xr[1] + fmaxf(v1, 0.f)) * actv;
                } else if (EPI == 0) {
                    v0 = cvt_tf32f(v0); v1 = cvt_tf32f(v1);
                }
                *reinterpret_cast<float2*>(Cb + (size_t)r * N + cc) = make_float2(v0, v1);
            }
        }
    }
}

// ---------------------------------------------------------------------------
// adjT: bit s of word (b,t,s/32) = (adj[b][s][t]!=0) | (s==t)
// ---------------------------------------------------------------------------
__global__ __launch_bounds__(1024) void adjT_kernel(const int* __restrict__ adj)
{
    __shared__ int sa[32][33];
    const int b = blockIdx.z, t0 = blockIdx.y * 32, s0 = blockIdx.x * 32;
    const int w = threadIdx.x >> 5, lane = threadIdx.x & 31;
    sa[w][lane] = adj[((size_t)b * NN + s0 + w) * NN + t0 + lane];
    __syncthreads();
    const int t = t0 + w;
    uint32_t word = __ballot_sync(0xFFFFFFFFu, sa[lane][w] != 0);
    if (lane == 0) {
        if ((t >> 5) == (s0 >> 5)) word |= 1u << (t & 31);
        g_adjT[((size_t)b * NN + t) * (NN / 32) + (s0 >> 5)] = word;
    }
}

// ---------------------------------------------------------------------------
// Weff = emb_W1 @ emb_W2 ; beff = emb_b1 @ emb_W2 + emb_b2
// ---------------------------------------------------------------------------
__global__ void prep_weff_kernel(const float* __restrict__ W1, const float* __restrict__ b1,
                                 const float* __restrict__ W2, const float* __restrict__ b2)
{
    int j = blockIdx.x * 256 + threadIdx.x;
    if (j >= HH) return;
    float acc[6] = {0.f, 0.f, 0.f, 0.f, 0.f, 0.f};
    float bacc = b2[j];
    for (int k = 0; k < HH; k++) {
        float w2 = W2[k * HH + j];
        bacc += b1[k] * w2;
#pragma unroll
        for (int i = 0; i < 6; i++) acc[i] += W1[i * HH + k] * w2;
    }
#pragma unroll
    for (int i = 0; i < 6; i++) g_Weff[i * HH + j] = acc[i];
    g_beff[j] = bacc;
}

// ---------------------------------------------------------------------------
// Feature construction + fused 6->512 embedding
// ---------------------------------------------------------------------------
__global__ void embed_kernel(const float* __restrict__ arr, const float* __restrict__ dep,
                             const float* __restrict__ hard,
                             const float* __restrict__ ts, const float* __restrict__ tt)
{
    int idx = blockIdx.x * 256 + threadIdx.x;
    int j = idx & (HH - 1);
    int row = idx >> 9;
    int b = row >> 11;
    float t = ts[b], T = tt[b];
    float ar = arr[row], de = dep[row];
    float f[6];
    f[0] = (t - ar) / (de - ar);
    f[1] = t / T;
    f[2] = fmodf(f[1], 2.f);
    f[3] = fmodf(f[1], 4.f);
    f[4] = fmodf(f[1], 7.f);
    f[5] = hard[row];
    float acc = g_beff[j];
#pragma unroll
    for (int i = 0; i < 6; i++) acc += f[i] * g_Weff[i * HH + j];
    g_x[idx] = acc;
}

// ---------------------------------------------------------------------------
// e_src / e_dst per row + per-batch max(e_src) via orderable-int atomicMax
// ---------------------------------------------------------------------------
__global__ void reset_smax_kernel()
{
    if (threadIdx.x < NB) g_smax_bits[threadIdx.x] = 0x007FFFFFu;  // enc(-inf)
}

__global__ void e_kernel(const float* __restrict__ asrc, const float* __restrict__ adst, int Fo)
{
    int row = blockIdx.x;
    const float* h = g_hw + (size_t)row * Fo;
    float ps = 0.f, pd = 0.f;
    for (int f = threadIdx.x; f < Fo; f += 128) {
        float v = h[f];
        ps += v * asrc[f];
        pd += v * adst[f];
    }
#pragma unroll
    for (int off = 16; off; off >>= 1) {
        ps += __shfl_xor_sync(0xFFFFFFFFu, ps, off);
        pd += __shfl_xor_sync(0xFFFFFFFFu, pd, off);
    }
    __shared__ float sp[4], sd[4];
    int w = threadIdx.x >> 5, l = threadIdx.x & 31;
    if (l == 0) { sp[w] = ps; sd[w] = pd; }
    __syncthreads();
    if (threadIdx.x == 0) {
        float es = sp[0] + sp[1] + sp[2] + sp[3];
        g_esrc[row] = es;
        g_edst[row] = sd[0] + sd[1] + sd[2] + sd[3];
        atomicMax(&g_smax_bits[row >> 11], enc_ord(es));
    }
}

// ---------------------------------------------------------------------------
// Per-node exp factors. All exponents <= 0 by construction (no overflow).
// P'(t,s) = valid * max(qa_t*f1_s, qb_t*f2_s)
// ---------------------------------------------------------------------------
__global__ void nodeprep_kernel()
{
    int t = blockIdx.x * 256 + threadIdx.x;
    int b = t >> 11;
    float sm = dec_ord(g_smax_bits[b]);
    float es = g_esrc[t], ed = g_edst[t];
    g_f1[t] = __expf(es - sm);
    g_f2[t] = __expf(0.2f * (es - sm));
    float u = ed + sm;
    float mh = fmaxf(u, 0.2f * u);
    g_qa[t] = __expf(u - mh);
    g_qb[t] = __expf(0.2f * u - mh);
}

// ---------------------------------------------------------------------------
// Materialize P' (tf32-rounded) + fused row-sum -> g_rz. One warp per row.
// ---------------------------------------------------------------------------
__global__ __launch_bounds__(256) void pgen_kernel()
{
    const int wid = threadIdx.x >> 5, lane = threadIdx.x & 31;
    const int t = blockIdx.x * 8 + wid;
    const int b = t >> 11;
    const float qa = g_qa[t], qb = g_qb[t];
    const uint32_t* wrow = g_adjT + (size_t)t * (NN / 32);
    const float* f1 = g_f1 + b * NN;
    const float* f2 = g_f2 + b * NN;
    float* Prow = g_P + (size_t)t * NN;
    float sum = 0.f;
#pragma unroll 4
    for (int i = 0; i < 16; i++) {
        const int s = i * 128 + lane * 4;
        const uint32_t w = wrow[s >> 5];
        const uint32_t sh = s & 31;
        float4 x1 = *reinterpret_cast<const float4*>(f1 + s);
        float4 x2 = *reinterpret_cast<const float4*>(f2 + s);
        float4 o;
        o.x = ((w >> (sh + 0)) & 1u) ? cvt_tf32f(fmaxf(qa * x1.x, qb * x2.x)) : 0.f;
        o.y = ((w >> (sh + 1)) & 1u) ? cvt_tf32f(fmaxf(qa * x1.y, qb * x2.y)) : 0.f;
        o.z = ((w >> (sh + 2)) & 1u) ? cvt_tf32f(fmaxf(qa * x1.z, qb * x2.z)) : 0.f;
        o.w = ((w >> (sh + 3)) & 1u) ? cvt_tf32f(fmaxf(qa * x1.w, qb * x2.w)) : 0.f;
        sum += (o.x + o.y) + (o.z + o.w);
        *reinterpret_cast<float4*>(Prow + s) = o;
    }
#pragma unroll
    for (int off = 16; off; off >>= 1) sum += __shfl_xor_sync(0xFFFFFFFFu, sum, off);
    if (lane == 0) g_rz[t] = 1.f / fmaxf(sum, 1e-30f);
}

// ---------------------------------------------------------------------------
// Host launcher
// ---------------------------------------------------------------------------
extern "C" void kernel_launch(void* const* d_in, const int* in_sizes, int n_in,
                              void* d_out, int out_size)
{
    const int*   adj      = (const int*)d_in[0];
    const float* arrivals = (const float*)d_in[1];
    const float* depart   = (const float*)d_in[2];
    const float* hard     = (const float*)d_in[3];
    const float* active   = (const float*)d_in[4];
    const float* timestep = (const float*)d_in[5];
    const float* totalts  = (const float*)d_in[6];
    const float* embW1 = (const float*)d_in[7];
    const float* embb1 = (const float*)d_in[8];
    const float* embW2 = (const float*)d_in[9];
    const float* embb2 = (const float*)d_in[10];
    const float* gatW[3]    = {(const float*)d_in[11], (const float*)d_in[15], (const float*)d_in[19]};
    const float* gatAsrc[3] = {(const float*)d_in[12], (const float*)d_in[16], (const float*)d_in[20]};
    const float* gatAdst[3] = {(const float*)d_in[13], (const float*)d_in[17], (const float*)d_in[21]};
    const float* gatB[3]    = {(const float*)d_in[14], (const float*)d_in[18], (const float*)d_in[22]};
    const float* ffW1 = (const float*)d_in[23];
    const float* ffb1 = (const float*)d_in[24];
    const float* ffW2 = (const float*)d_in[25];
    const float* ffb2 = (const float*)d_in[26];

    float *x, *h, *hw, *P, *rz;
    cudaGetSymbolAddress((void**)&x,  g_x);
    cudaGetSymbolAddress((void**)&h,  g_h);
    cudaGetSymbolAddress((void**)&hw, g_hw);
    cudaGetSymbolAddress((void**)&P,  g_P);
    cudaGetSymbolAddress((void**)&rz, g_rz);

    static int smem_set = 0;
    if (!smem_set) {
        cudaFuncSetAttribute(gemm_tc<0>, cudaFuncAttributeMaxDynamicSharedMemorySize, SMEM_BYTES);
        cudaFuncSetAttribute(gemm_tc<1>, cudaFuncAttributeMaxDynamicSharedMemorySize, SMEM_BYTES);
        cudaFuncSetAttribute(gemm_tc<2>, cudaFuncAttributeMaxDynamicSharedMemorySize, SMEM_BYTES);
        cudaFuncSetAttribute(gemm_tc<3>, cudaFuncAttributeMaxDynamicSharedMemorySize, SMEM_BYTES);
        cudaFuncSetAttribute(gemm_tc<4>, cudaFuncAttributeMaxDynamicSharedMemorySize, SMEM_BYTES);
        smem_set = 1;
    }

    prep_weff_kernel<<<2, 256>>>(embW1, embb1, embW2, embb2);
    embed_kernel<<<(MROWS * HH) / 256, 256>>>(arrivals, depart, hard, timestep, totalts);
    adjT_kernel<<<dim3(NN / 32, NN / 32, NB), 1024>>>(adj);

    const int Kin[3] = {HH, 1024, 1024};
    const int Fo[3]  = {1024, 1024, HH};

    for (int l = 0; l < 3; l++) {
        const float* hin = (l == 0) ? x : h;
        // hw = hin @ W  (tf32-rounded store)
        gemm_tc<0><<<dim3(Fo[l] / 128, MROWS / 128), 256, SMEM_BYTES>>>(
            hin, gatW[l], hw, Kin[l], Fo[l], nullptr, nullptr, nullptr, nullptr);
        reset_smax_kernel<<<1, 32>>>();
        e_kernel<<<MROWS, 128>>>(gatAsrc[l], gatAdst[l], Fo[l]);
        nodeprep_kernel<<<MROWS / 256, 256>>>();
        pgen_kernel<<<MROWS / 8, 256>>>();
        if (l < 2) {
            gemm_tc<1><<<dim3(Fo[l] / 128, NN / 128, NB), 256, SMEM_BYTES>>>(
                P, hw, h, NN, Fo[l], gatB[l], nullptr, nullptr, rz);
        } else {
            gemm_tc<2><<<dim3(Fo[l] / 128, NN / 128, NB), 256, SMEM_BYTES>>>(
                P, hw, h, NN, Fo[l], gatB[l], x, nullptr, rz);
        }
    }

    // ff1: x2 = x1 + relu(x1 @ W1 + b1)
    gemm_tc<3><<<dim3(HH / 128, MROWS / 128), 256, SMEM_BYTES>>>(
        h, ffW1, x, HH, HH, ffb1, h, nullptr, nullptr);
    // ff2: out = (x2 + relu(x2 @ W2 + b2)) * active
    gemm_tc<4><<<dim3(HH / 128, MROWS / 128), 256, SMEM_BYTES>>>(
        x, ffW2, (float*)d_out, HH, HH, ffb2, x, active, nullptr);
}

// round 5
// speedup vs baseline: 2.7715x; 1.0829x over previous
#include <cuda_runtime.h>
#include <cstdint>

#define NB 8
#define NN 2048
#define HH 512
#define MROWS (NB * NN)   // 16384

// ---------------------------------------------------------------------------
// Scratch (device globals — no allocation allowed)
// ---------------------------------------------------------------------------
__device__ float g_x[MROWS * HH];                 // embedding output / residual
__device__ float g_h[MROWS * 1024];               // layer activations
__device__ float g_hwt[1024 * MROWS];             // (h @ W)^T  [Fo][MROWS], tf32-rounded
__device__ float g_P[(size_t)MROWS * NN];         // unnormalized attention (tf32-rounded)
__device__ float g_wt[1024 * 1024];               // transposed weight [N][K]
__device__ uint32_t g_adjT[MROWS * (NN / 32)];    // bit: valid(t, s), self-loop folded
__device__ float g_esrc[MROWS], g_edst[MROWS];
__device__ float g_f1[MROWS], g_f2[MROWS];        // per-source exp factors
__device__ float g_qa[MROWS], g_qb[MROWS];        // per-target exp factors
__device__ float g_rz[MROWS];                     // 1 / row-sum of P'
__device__ unsigned int g_smax_bits[NB];          // orderable-int max of esrc per batch
__device__ float g_Weff[6 * HH];
__device__ float g_beff[HH];

// ---------------------------------------------------------------------------
// Helpers
// ---------------------------------------------------------------------------
__device__ __forceinline__ float cvt_tf32f(float x) {
    uint32_t r;
    asm("cvt.rna.tf32.f32 %0, %1;" : "=r"(r) : "f"(x));
    return __uint_as_float(r);
}
__device__ __forceinline__ unsigned enc_ord(float f) {
    unsigned i = __float_as_uint(f);
    return (i & 0x80000000u) ? ~i : (i | 0x80000000u);
}
__device__ __forceinline__ float dec_ord(unsigned k) {
    unsigned i = (k & 0x80000000u) ? (k & 0x7FFFFFFFu) : ~k;
    return __uint_as_float(i);
}
__device__ __forceinline__ uint32_t smem_u32(const void* p) {
    uint32_t a;
    asm("{ .reg .u64 t; cvta.to.shared.u64 t, %1; cvt.u32.u64 %0, t; }" : "=r"(a) : "l"(p));
    return a;
}
__device__ __forceinline__ void mma8u(float* c, const uint32_t* a, uint32_t b0, uint32_t b1) {
    asm volatile(
        "mma.sync.aligned.m16n8k8.row.col.f32.tf32.tf32.f32 "
        "{%0,%1,%2,%3}, {%4,%5,%6,%7}, {%8,%9}, {%0,%1,%2,%3};"
        : "+f"(c[0]), "+f"(c[1]), "+f"(c[2]), "+f"(c[3])
        : "r"(a[0]), "r"(a[1]), "r"(a[2]), "r"(a[3]), "r"(b0), "r"(b1));
}
__device__ __forceinline__ void ldsm4(uint32_t* r, uint32_t addr) {
    asm volatile("ldmatrix.sync.aligned.m8n8.x4.shared.b16 {%0,%1,%2,%3}, [%4];"
                 : "=r"(r[0]), "=r"(r[1]), "=r"(r[2]), "=r"(r[3]) : "r"(addr));
}
#define CPA(dst, src) asm volatile("cp.async.cg.shared.global [%0], [%1], 16;" :: "r"(dst), "l"(src))
#define CPC() asm volatile("cp.async.commit_group;")
#define CPW(n) asm volatile("cp.async.wait_group %0;" :: "n"(n))

// k-major swizzled tile: row (m or n) = 0..127, 32 floats (8 float4) per row.
// float offset of float4 (row, c4): row*32 + ((c4 ^ (row&7)) << 2)
#define SOFF(row, c4) ((row) * 32 + (((c4) ^ ((row) & 7)) << 2))

#define STAGE_BYTES 32768                 // A 16KB + B 16KB
#define SMEM_BYTES (3 * STAGE_BYTES)      // 3 stages (async path); CVT uses 2

// ---------------------------------------------------------------------------
// Unified tf32 tensor-core GEMM. C[M,N] = A[M,K] @ Bt^T. Bt is [N][K] k-contig.
// EPI 0: Ct[n][m] = cvt_tf32(acc)                (writes transposed -> hwt)
// EPI 1: C = relu(acc*rz + bias)                 (attention, batched, cp.async)
// EPI 2: C = acc*rz + bias + X                   (attention last, batched, cp.async)
// EPI 3: C = X + relu(acc + bias)                (ff1)
// EPI 4: C = (X + relu(acc + bias)) * act[row]   (ff2)
// ---------------------------------------------------------------------------
template <int EPI>
__global__ __launch_bounds__(256, 2) void gemm_tc(
    const float* __restrict__ A, const float* __restrict__ Bt, float* __restrict__ C,
    int K, int N, const float* __restrict__ bias, const float* __restrict__ X,
    const float* __restrict__ act, const float* __restrict__ rz)
{
    constexpr bool BATCHED = (EPI == 1 || EPI == 2);   // async, pre-tf32 operands
    extern __shared__ float smf[];
    const uint32_t sbase = smem_u32(smf);
    const int tid = threadIdx.x;
    const int lane = tid & 31, wid = tid >> 5;

    // CTA rasterization swizzle: groups of 4 m-rows x full n share L2
    int bx = blockIdx.x, by = blockIdx.y;
    {
        const int GX = gridDim.x;
        const int lin = by * GX + bx;
        const int grp = lin / (4 * GX);
        const int rem = lin - grp * 4 * GX;
        by = grp * 4 + (rem & 3);
        bx = rem >> 2;
    }
    const int m0 = by * 128, n0 = bx * 128;
    const int ws = wid >> 2, wcs = wid & 3;
    const int wm = ws * 64, wn = wcs * 32;

    size_t zoff = 0;
    if (BATCHED) zoff = (size_t)blockIdx.z * NN;
    const float* Ab = A + zoff * K;             // A row-major, k contiguous
    const int ldb = BATCHED ? MROWS : K;        // Bt leading dim
    const int kboff = BATCHED ? (int)zoff : 0;  // Bt column offset (batch rows)
    float* Cb = C + zoff * N;
    const float* Xb = (EPI >= 2) ? X + zoff * N : nullptr;
    const float* rzb = BATCHED ? rz + zoff : nullptr;

    float acc[4][4][4];
#pragma unroll
    for (int i = 0; i < 4; i++)
#pragma unroll
        for (int j = 0; j < 4; j++)
#pragma unroll
            for (int q = 0; q < 4; q++) acc[i][j][q] = 0.f;

    const int row_l = tid >> 3, c4_l = tid & 7;   // this thread's ldg/sts slot (p stride 32 rows)

    // ---- compute one k-tile from stage stg ----
    auto compute = [&](int stg) {
        const uint32_t aB = sbase + stg * STAGE_BYTES;
        const uint32_t bB = aB + 16384;
        const int mA = lane & 15, cA = lane >> 4;
        const int nB = (lane & 7) + ((lane >> 4) << 3), cB = (lane >> 3) & 1;
#pragma unroll
        for (int kk = 0; kk < 4; kk++) {
            uint32_t fa[4][4], fb[2][4];
#pragma unroll
            for (int mf = 0; mf < 4; mf++) {
                const int m = wm + mf * 16 + mA;
                ldsm4(fa[mf], aB + SOFF(m, kk * 2 + cA) * 4);
            }
#pragma unroll
            for (int nfp = 0; nfp < 2; nfp++) {
                const int n = wn + nfp * 16 + nB;
                ldsm4(fb[nfp], bB + SOFF(n, kk * 2 + cB) * 4);
            }
#pragma unroll
            for (int mf = 0; mf < 4; mf++)
#pragma unroll
                for (int nf = 0; nf < 4; nf++)
                    mma8u(acc[mf][nf], fa[mf], fb[nf >> 1][(nf & 1) * 2],
                          fb[nf >> 1][(nf & 1) * 2 + 1]);
        }
    };

    const int nkt = K >> 5;

    if (BATCHED) {
        // ---- cp.async 3-stage pipeline (operands pre-tf32) ----
        auto issue = [&](int kt) {
            const int stg = kt % 3;
            const int k0 = kt << 5;
            const uint32_t aB = sbase + stg * STAGE_BYTES;
            const uint32_t bB = aB + 16384;
#pragma unroll
            for (int p = 0; p < 4; p++) {
                const int row = row_l + p * 32;
                const uint32_t so = SOFF(row, c4_l) * 4;
                CPA(aB + so, Ab + (size_t)(m0 + row) * K + k0 + c4_l * 4);
                CPA(bB + so, Bt + (size_t)(n0 + row) * ldb + kboff + k0 + c4_l * 4);
            }
        };
        issue(0); CPC();
        issue(1); CPC();
        for (int kt = 0; kt < nkt; kt++) {
            if (kt < nkt - 1) { CPW(1); } else { CPW(0); }
            __syncthreads();
            if (kt + 2 < nkt) { issue(kt + 2); CPC(); }
            compute(kt % 3);
        }
    } else {
        // ---- register double-buffer with cvt.rna on the way in ----
        float4 va[4], vb[4];
        auto ldg = [&](int k0) {
#pragma unroll
            for (int p = 0; p < 4; p++) {
                const int row = row_l + p * 32;
                va[p] = *reinterpret_cast<const float4*>(Ab + (size_t)(m0 + row) * K + k0 + c4_l * 4);
                vb[p] = *reinterpret_cast<const float4*>(Bt + (size_t)(n0 + row) * ldb + k0 + c4_l * 4);
            }
#pragma unroll
            for (int p = 0; p < 4; p++) {
                va[p].x = cvt_tf32f(va[p].x); va[p].y = cvt_tf32f(va[p].y);
                va[p].z = cvt_tf32f(va[p].z); va[p].w = cvt_tf32f(va[p].w);
                vb[p].x = cvt_tf32f(vb[p].x); vb[p].y = cvt_tf32f(vb[p].y);
                vb[p].z = cvt_tf32f(vb[p].z); vb[p].w = cvt_tf32f(vb[p].w);
            }
        };
        auto sts = [&](int stg) {
            float* sA = smf + stg * 8192;
            float* sB = sA + 4096;
#pragma unroll
            for (int p = 0; p < 4; p++) {
                const int row = row_l + p * 32;
                const int so = SOFF(row, c4_l);
                *reinterpret_cast<float4*>(sA + so) = va[p];
                *reinterpret_cast<float4*>(sB + so) = vb[p];
            }
        };
        ldg(0);
        sts(0);
        __syncthreads();
        for (int kt = 0; kt < nkt; kt++) {
            if (kt + 1 < nkt) ldg((kt + 1) << 5);
            compute(kt & 1);
            if (kt + 1 < nkt) {
                sts((kt + 1) & 1);
                __syncthreads();
            }
        }
    }

    // ---- epilogue ----
#pragma unroll
    for (int mf = 0; mf < 4; mf++) {
#pragma unroll
        for (int rr = 0; rr < 2; rr++) {
            const int r = m0 + wm + mf * 16 + (lane >> 2) + rr * 8;
            float rzv = 1.f, actv = 1.f;
            if (BATCHED) rzv = rzb[r];
            if (EPI == 4) actv = act[r];
#pragma unroll
            for (int nf = 0; nf < 4; nf++) {
                const int cc = n0 + wn + nf * 8 + (lane & 3) * 2;
                float v0 = acc[mf][nf][rr * 2 + 0];
                float v1 = acc[mf][nf][rr * 2 + 1];
                if (EPI == 0) {
                    // transposed store: Ct[n][m] (hwt), tf32-rounded
                    C[(size_t)cc * MROWS + r]       = cvt_tf32f(v0);
                    C[(size_t)(cc + 1) * MROWS + r] = cvt_tf32f(v1);
                } else {
                    if (BATCHED) { v0 *= rzv; v1 *= rzv; }
                    v0 += bias[cc]; v1 += bias[cc + 1];
                    if (EPI == 1) { v0 = fmaxf(v0, 0.f); v1 = fmaxf(v1, 0.f); }
                    else if (EPI == 2) {
                        const float* xr = Xb + (size_t)r * N + cc;
                        v0 += xr[0]; v1 += xr[1];
                    } else if (EPI == 3) {
                        const float* xr = Xb + (size_t)r * N + cc;
                        v0 = xr[0] + fmaxf(v0, 0.f); v1 = xr[1] + fmaxf(v1, 0.f);
                    } else if (EPI == 4) {
                        const float* xr = Xb + (size_t)r * N + cc;
                        v0 = (xr[0] + fmaxf(v0, 0.f)) * actv;
                        v1 = (xr[1] + fmaxf(v1, 0.f)) * actv;
                    }
                    *reinterpret_cast<float2*>(Cb + (size_t)r * N + cc) = make_float2(v0, v1);
                }
            }
        }
    }
}

// ---------------------------------------------------------------------------
// 32x32 tiled transpose: out[C][R] = in[R][C]^T
// ---------------------------------------------------------------------------
__global__ void transpose_kernel(const float* __restrict__ in, float* __restrict__ out,
                                 int R, int Cc)
{
    __shared__ float tile[32][33];
    int c0 = blockIdx.x * 32, r0 = blockIdx.y * 32;
    int x = threadIdx.x, y = threadIdx.y;
#pragma unroll
    for (int i = 0; i < 32; i += 8)
        tile[y + i][x] = in[(size_t)(r0 + y + i) * Cc + c0 + x];
    __syncthreads();
#pragma unroll
    for (int i = 0; i < 32; i += 8)
        out[(size_t)(c0 + y + i) * R + r0 + x] = tile[x][y + i];
}

// ---------------------------------------------------------------------------
// adjT: bit s of word (b,t,s/32) = (adj[b][s][t]!=0) | (s==t)
// ---------------------------------------------------------------------------
__global__ __launch_bounds__(1024) void adjT_kernel(const int* __restrict__ adj)
{
    __shared__ int sa[32][33];
    const int b = blockIdx.z, t0 = blockIdx.y * 32, s0 = blockIdx.x * 32;
    const int w = threadIdx.x >> 5, lane = threadIdx.x & 31;
    sa[w][lane] = adj[((size_t)b * NN + s0 + w) * NN + t0 + lane];
    __syncthreads();
    const int t = t0 + w;
    uint32_t word = __ballot_sync(0xFFFFFFFFu, sa[lane][w] != 0);
    if (lane == 0) {
        if ((t >> 5) == (s0 >> 5)) word |= 1u << (t & 31);
        g_adjT[((size_t)b * NN + t) * (NN / 32) + (s0 >> 5)] = word;
    }
}

// ---------------------------------------------------------------------------
// Weff = emb_W1 @ emb_W2 ; beff = emb_b1 @ emb_W2 + emb_b2
// ---------------------------------------------------------------------------
__global__ void prep_weff_kernel(const float* __restrict__ W1, const float* __restrict__ b1,
                                 const float* __restrict__ W2, const float* __restrict__ b2)
{
    int j = blockIdx.x * 256 + threadIdx.x;
    if (j >= HH) return;
    float acc[6] = {0.f, 0.f, 0.f, 0.f, 0.f, 0.f};
    float bacc = b2[j];
    for (int k = 0; k < HH; k++) {
        float w2 = W2[k * HH + j];
        bacc += b1[k] * w2;
#pragma unroll
        for (int i = 0; i < 6; i++) acc[i] += W1[i * HH + k] * w2;
    }
#pragma unroll
    for (int i = 0; i < 6; i++) g_Weff[i * HH + j] = acc[i];
    g_beff[j] = bacc;
}

// ---------------------------------------------------------------------------
// Feature construction + fused 6->512 embedding
// ---------------------------------------------------------------------------
__global__ void embed_kernel(const float* __restrict__ arr, const float* __restrict__ dep,
                             const float* __restrict__ hard,
                             const float* __restrict__ ts, const float* __restrict__ tt)
{
    int idx = blockIdx.x * 256 + threadIdx.x;
    int j = idx & (HH - 1);
    int row = idx >> 9;
    int b = row >> 11;
    float t = ts[b], T = tt[b];
    float ar = arr[row], de = dep[row];
    float f[6];
    f[0] = (t - ar) / (de - ar);
    f[1] = t / T;
    f[2] = fmodf(f[1], 2.f);
    f[3] = fmodf(f[1], 4.f);
    f[4] = fmodf(f[1], 7.f);
    f[5] = hard[row];
    float acc = g_beff[j];
#pragma unroll
    for (int i = 0; i < 6; i++) acc += f[i] * g_Weff[i * HH + j];
    g_x[idx] = acc;
}

// ---------------------------------------------------------------------------
// e_src / e_dst from hwt (coalesced columns) + per-batch max via atomicMax
// ---------------------------------------------------------------------------
__global__ void reset_smax_kernel()
{
    if (threadIdx.x < NB) g_smax_bits[threadIdx.x] = 0x007FFFFFu;  // enc(-inf)
}

__global__ __launch_bounds__(256) void e2_kernel(const float* __restrict__ asrc,
                                                 const float* __restrict__ adst, int Fo)
{
    __shared__ float sa[1024], sd[1024];
    const int tid = threadIdx.x;
    for (int f = tid; f < Fo; f += 256) { sa[f] = asrc[f]; sd[f] = adst[f]; }
    __syncthreads();
    const int r = blockIdx.x * 256 + tid;
    const float* col = g_hwt + r;
    float ps = 0.f, pd = 0.f;
    for (int f = 0; f < Fo; f += 4) {
        float v0 = col[(size_t)(f + 0) * MROWS];
        float v1 = col[(size_t)(f + 1) * MROWS];
        float v2 = col[(size_t)(f + 2) * MROWS];
        float v3 = col[(size_t)(f + 3) * MROWS];
        ps += v0 * sa[f] + v1 * sa[f + 1] + v2 * sa[f + 2] + v3 * sa[f + 3];
        pd += v0 * sd[f] + v1 * sd[f + 1] + v2 * sd[f + 2] + v3 * sd[f + 3];
    }
    g_esrc[r] = ps;
    g_edst[r] = pd;
    __shared__ float red[256];
    red[tid] = ps;
    __syncthreads();
    for (int s = 128; s; s >>= 1) {
        if (tid < s) red[tid] = fmaxf(red[tid], red[tid + s]);
        __syncthreads();
    }
    if (tid == 0) atomicMax(&g_smax_bits[r >> 11], enc_ord(red[0]));
}

// ---------------------------------------------------------------------------
// Per-node exp factors (all exponents <= 0 -> no overflow)
// ---------------------------------------------------------------------------
__global__ void nodeprep_kernel()
{
    int t = blockIdx.x * 256 + threadIdx.x;
    int b = t >> 11;
    float sm = dec_ord(g_smax_bits[b]);
    float es = g_esrc[t], ed = g_edst[t];
    g_f1[t] = __expf(es - sm);
    g_f2[t] = __expf(0.2f * (es - sm));
    float u = ed + sm;
    float mh = fmaxf(u, 0.2f * u);
    g_qa[t] = __expf(u - mh);
    g_qb[t] = __expf(0.2f * u - mh);
}

// ---------------------------------------------------------------------------
// Materialize P' (tf32-rounded) + fused row-sum -> g_rz. One warp per row.
// ---------------------------------------------------------------------------
__global__ __launch_bounds__(256) void pgen_kernel()
{
    const int wid = threadIdx.x >> 5, lane = threadIdx.x & 31;
    const int t = blockIdx.x * 8 + wid;
    const int b = t >> 11;
    const float qa = g_qa[t], qb = g_qb[t];
    const uint32_t* wrow = g_adjT + (size_t)t * (NN / 32);
    const float* f1 = g_f1 + b * NN;
    const float* f2 = g_f2 + b * NN;
    float* Prow = g_P + (size_t)t * NN;
    float sum = 0.f;
#pragma unroll 4
    for (int i = 0; i < 16; i++) {
        const int s = i * 128 + lane * 4;
        const uint32_t w = wrow[s >> 5];
        const uint32_t sh = s & 31;
        float4 x1 = *reinterpret_cast<const float4*>(f1 + s);
        float4 x2 = *reinterpret_cast<const float4*>(f2 + s);
        float4 o;
        o.x = ((w >> (sh + 0)) & 1u) ? cvt_tf32f(fmaxf(qa * x1.x, qb * x2.x)) : 0.f;
        o.y = ((w >> (sh + 1)) & 1u) ? cvt_tf32f(fmaxf(qa * x1.y, qb * x2.y)) : 0.f;
        o.z = ((w >> (sh + 2)) & 1u) ? cvt_tf32f(fmaxf(qa * x1.z, qb * x2.z)) : 0.f;
        o.w = ((w >> (sh + 3)) & 1u) ? cvt_tf32f(fmaxf(qa * x1.w, qb * x2.w)) : 0.f;
        sum += (o.x + o.y) + (o.z + o.w);
        *reinterpret_cast<float4*>(Prow + s) = o;
    }
#pragma unroll
    for (int off = 16; off; off >>= 1) sum += __shfl_xor_sync(0xFFFFFFFFu, sum, off);
    if (lane == 0) g_rz[t] = 1.f / fmaxf(sum, 1e-30f);
}

// ---------------------------------------------------------------------------
// Host launcher
// ---------------------------------------------------------------------------
extern "C" void kernel_launch(void* const* d_in, const int* in_sizes, int n_in,
                              void* d_out, int out_size)
{
    const int*   adj      = (const int*)d_in[0];
    const float* arrivals = (const float*)d_in[1];
    const float* depart   = (const float*)d_in[2];
    const float* hard     = (const float*)d_in[3];
    const float* active   = (const float*)d_in[4];
    const float* timestep = (const float*)d_in[5];
    const float* totalts  = (const float*)d_in[6];
    const float* embW1 = (const float*)d_in[7];
    const float* embb1 = (const float*)d_in[8];
    const float* embW2 = (const float*)d_in[9];
    const float* embb2 = (const float*)d_in[10];
    const float* gatW[3]    = {(const float*)d_in[11], (const float*)d_in[15], (const float*)d_in[19]};
    const float* gatAsrc[3] = {(const float*)d_in[12], (const float*)d_in[16], (const float*)d_in[20]};
    const float* gatAdst[3] = {(const float*)d_in[13], (const float*)d_in[17], (const float*)d_in[21]};
    const float* gatB[3]    = {(const float*)d_in[14], (const float*)d_in[18], (const float*)d_in[22]};
    const float* ffW1 = (const float*)d_in[23];
    const float* ffb1 = (const float*)d_in[24];
    const float* ffW2 = (const float*)d_in[25];
    const float* ffb2 = (const float*)d_in[26];

    float *x, *h, *hwt, *P, *rz, *wt;
    cudaGetSymbolAddress((void**)&x,   g_x);
    cudaGetSymbolAddress((void**)&h,   g_h);
    cudaGetSymbolAddress((void**)&hwt, g_hwt);
    cudaGetSymbolAddress((void**)&P,   g_P);
    cudaGetSymbolAddress((void**)&rz,  g_rz);
    cudaGetSymbolAddress((void**)&wt,  g_wt);

    static int smem_set = 0;
    if (!smem_set) {
        cudaFuncSetAttribute(gemm_tc<0>, cudaFuncAttributeMaxDynamicSharedMemorySize, SMEM_BYTES);
        cudaFuncSetAttribute(gemm_tc<1>, cudaFuncAttributeMaxDynamicSharedMemorySize, SMEM_BYTES);
        cudaFuncSetAttribute(gemm_tc<2>, cudaFuncAttributeMaxDynamicSharedMemorySize, SMEM_BYTES);
        cudaFuncSetAttribute(gemm_tc<3>, cudaFuncAttributeMaxDynamicSharedMemorySize, SMEM_BYTES);
        cudaFuncSetAttribute(gemm_tc<4>, cudaFuncAttributeMaxDynamicSharedMemorySize, SMEM_BYTES);
        smem_set = 1;
    }

    prep_weff_kernel<<<2, 256>>>(embW1, embb1, embW2, embb2);
    embed_kernel<<<(MROWS * HH) / 256, 256>>>(arrivals, depart, hard, timestep, totalts);
    adjT_kernel<<<dim3(NN / 32, NN / 32, NB), 1024>>>(adj);

    const int Kin[3] = {HH, 1024, 1024};
    const int Fo[3]  = {1024, 1024, HH};
    const dim3 tblk(32, 8);

    for (int l = 0; l < 3; l++) {
        const float* hin = (l == 0) ? x : h;
        // wt = W^T [Fo][Kin]
        transpose_kernel<<<dim3(Fo[l] / 32, Kin[l] / 32), tblk>>>(gatW[l], wt, Kin[l], Fo[l]);
        // hwt = (hin @ W)^T  (written transposed, tf32-rounded)
        gemm_tc<0><<<dim3(Fo[l] / 128, MROWS / 128), 256, SMEM_BYTES>>>(
            hin, wt, hwt, Kin[l], Fo[l], nullptr, nullptr, nullptr, nullptr);
        reset_smax_kernel<<<1, 32>>>();
        e2_kernel<<<MROWS / 256, 256>>>(gatAsrc[l], gatAdst[l], Fo[l]);
        nodeprep_kernel<<<MROWS / 256, 256>>>();
        pgen_kernel<<<MROWS / 8, 256>>>();
        if (l < 2) {
            gemm_tc<1><<<dim3(Fo[l] / 128, NN / 128, NB), 256, SMEM_BYTES>>>(
                P, hwt, h, NN, Fo[l], gatB[l], nullptr, nullptr, rz);
        } else {
            gemm_tc<2><<<dim3(Fo[l] / 128, NN / 128, NB), 256, SMEM_BYTES>>>(
                P, hwt, h, NN, Fo[l], gatB[l], x, nullptr, rz);
        }
    }

    // ff1: x2 = x1 + relu(x1 @ W1 + b1)
    transpose_kernel<<<dim3(HH / 32, HH / 32), tblk>>>(ffW1, wt, HH, HH);
    gemm_tc<3><<<dim3(HH / 128, MROWS / 128), 256, SMEM_BYTES>>>(
        h, wt, x, HH, HH, ffb1, h, nullptr, nullptr);
    // ff2: out = (x2 + relu(x2 @ W2 + b2)) * active
    transpose_kernel<<<dim3(HH / 32, HH / 32), tblk>>>(ffW2, wt, HH, HH);
    gemm_tc<4><<<dim3(HH / 128, MROWS / 128), 256, SMEM_BYTES>>>(
        x, wt, (float*)d_out, HH, HH, ffb2, x, active, nullptr);
}